// round 5
// baseline (speedup 1.0000x reference)
#include <cuda_runtime.h>

// NotearsRKHS on GB300 (sm_103a).
// out[i,j] = sum_l K[j,i,l] * ( alpha[j,l] + 2*sum_{a!=j} beta[j,a,l]*diff[i,l,a] )
// K[j,i,l] = exp(diff[i,l,j]^2 - S[i,l]),  S = full squared distance. GAMMA=1.
// x:[N,D] f32, alpha:[D,N] f32, beta:[D,D,N] f32, out:[N,D] f32. N=2000, D=24.
//
// Design: IPT=1, 128 threads, forced occupancy 4 (16 warps/SM, 4/SMSP),
// grid 16x37 = 592 CTAs = exactly one wave at 148 SM x occ4. Beta diagonal
// zeroed in smem at tile-load time. All math packed fp32x2 (Blackwell FFMA2,
// PTX-only) except two MUFU.EX2 per j-pair. Deterministic split-l reduction
// through a __device__ partial buffer (no float atomics, no allocation).

#define NN 2000
#define DD 24
#define BLK 128
#define NIB 16            // 16 * 128 = 2048 >= 2000 i-rows
#define LSPLIT 37         // 16 * 37 = 592 CTAs = 148 SM * occ4, one exact wave
#define CHUNK 56          // 37 * 56 = 2072 >= 2000 (tail zero-padded)
#define TL 14             // l-tile in shared
#define NTILES 4          // 56 / 14
#define BROW 580          // padded beta_s row stride (floats), 16B multiple

#define L2E 1.4426950408889634f

__device__ float g_partial[LSPLIT * NN * DD];

typedef unsigned long long u64;

__device__ __forceinline__ u64 pack2(float lo, float hi) {
    u64 r; asm("mov.b64 %0, {%1,%2};" : "=l"(r) : "f"(lo), "f"(hi)); return r;
}
__device__ __forceinline__ void unpack2(u64 v, float& lo, float& hi) {
    asm("mov.b64 {%0,%1}, %2;" : "=f"(lo), "=f"(hi) : "l"(v));
}
__device__ __forceinline__ u64 ffma2(u64 a, u64 b, u64 c) {
    u64 d; asm("fma.rn.f32x2 %0, %1, %2, %3;" : "=l"(d) : "l"(a), "l"(b), "l"(c)); return d;
}
__device__ __forceinline__ u64 add2(u64 a, u64 b) {
    u64 d; asm("add.rn.f32x2 %0, %1, %2;" : "=l"(d) : "l"(a), "l"(b)); return d;
}
__device__ __forceinline__ u64 mul2(u64 a, u64 b) {
    u64 d; asm("mul.rn.f32x2 %0, %1, %2;" : "=l"(d) : "l"(a), "l"(b)); return d;
}
__device__ __forceinline__ float ex2f(float a) {
    float r; asm("ex2.approx.ftz.f32 %0, %1;" : "=f"(r) : "f"(a)); return r;
}

__global__ __launch_bounds__(BLK, 4)
void notears_main(const float* __restrict__ x,
                  const float* __restrict__ alpha,
                  const float* __restrict__ beta)
{
    __shared__ __align__(16) float beta_s[TL * BROW];  // [lt][j*24+a], diag zeroed
    __shared__ __align__(16) float nxl_s[TL * 24];     // negated x[l] tile
    __shared__ __align__(16) float al_s[TL * 24];      // alpha[j,l] tile, [lt][j]

    const int tid = threadIdx.x;
    const int i = blockIdx.x * BLK + tid;
    const int l_base = blockIdx.y * CHUNK;

    const u64 TWO2 = pack2(2.0f, 2.0f);
    const u64 L2E2 = pack2(L2E, L2E);

    // per-thread x row, packed (zeros for tail threads)
    u64 xi2[12];
    {
        const float4* xr = (const float4*)(x + (size_t)i * DD);
        #pragma unroll
        for (int q = 0; q < 6; q++) {
            float4 v = (i < NN) ? xr[q] : make_float4(0.f, 0.f, 0.f, 0.f);
            xi2[2*q]   = pack2(v.x, v.y);
            xi2[2*q+1] = pack2(v.z, v.w);
        }
    }

    u64 acc2[12];
    #pragma unroll
    for (int p = 0; p < 12; p++) acc2[p] = 0ull;

    for (int tile = 0; tile < NTILES; tile++) {
        const int l0 = l_base + tile * TL;
        __syncthreads();
        // beta tile: beta_s[lt*BROW + ja] = beta[ja*NN + l]; zero-pad l >= NN;
        // zero the (a==j) diagonal here (ja % 25 == 0) so the matvec needs no fixup.
        for (int idx = tid; idx < 576 * (TL / 2); idx += BLK) {
            int ja = idx / (TL / 2);
            int p  = idx - ja * (TL / 2);
            int lt = 2 * p;
            int l  = l0 + lt;
            float2 v;
            if (l + 2 <= NN) {
                v = *(const float2*)(beta + (size_t)ja * NN + l);
            } else {
                v.x = (l     < NN) ? beta[(size_t)ja * NN + l]     : 0.0f;
                v.y = (l + 1 < NN) ? beta[(size_t)ja * NN + l + 1] : 0.0f;
            }
            if (ja % 25 == 0) { v.x = 0.0f; v.y = 0.0f; }   // diagonal beta[j,j,:]
            beta_s[lt * BROW + ja]       = v.x;
            beta_s[(lt + 1) * BROW + ja] = v.y;
        }
        // negated x[l] tile
        for (int idx = tid; idx < TL * 24; idx += BLK) {
            int lt = idx / 24;
            int k  = idx - lt * 24;
            int l  = l0 + lt;
            nxl_s[idx] = (l < NN) ? -x[(size_t)l * DD + k] : 0.0f;
        }
        // alpha tile (zero-pad -> padded l contributes exactly 0)
        for (int idx = tid; idx < TL * 24; idx += BLK) {
            int lt = idx / 24;
            int j  = idx - lt * 24;
            int l  = l0 + lt;
            al_s[lt * 24 + j] = (l < NN) ? alpha[(size_t)j * NN + l] : 0.0f;
        }
        __syncthreads();

        #pragma unroll 1
        for (int lt = 0; lt < TL; lt++) {
            // packed diffs + squared distance S
            const ulonglong2* nx2 = (const ulonglong2*)&nxl_s[lt * 24];
            u64 df2[12];
            u64 sa = 0ull, sb = 0ull;
            #pragma unroll
            for (int q = 0; q < 6; q++) {
                ulonglong2 v = nx2[q];
                u64 d0 = add2(xi2[2*q],   v.x); df2[2*q]   = d0; sa = ffma2(d0, d0, sa);
                u64 d1 = add2(xi2[2*q+1], v.y); df2[2*q+1] = d1; sb = ffma2(d1, d1, sb);
            }
            float slo, shi;
            unpack2(add2(sa, sb), slo, shi);
            const float S = slo + shi;
            const float m = -S * L2E;
            const u64 nS2 = pack2(m, m);

            const float* bb   = &beta_s[lt * BROW];
            const float* arow = &al_s[lt * 24];

            #pragma unroll
            for (int jp = 0; jp < 12; jp++) {
                const int j0 = 2 * jp;
                const ulonglong2* b0 = (const ulonglong2*)(bb + j0 * 24);
                const ulonglong2* b1 = (const ulonglong2*)(bb + (j0 + 1) * 24);
                // tt[j] = sum_a beta~[j,a]*diff[a]  (diag already zero)
                u64 t0a = 0ull, t0b = 0ull, t1a = 0ull, t1b = 0ull;
                #pragma unroll
                for (int q = 0; q < 6; q++) {
                    ulonglong2 v0 = b0[q];   // broadcast LDS.128
                    ulonglong2 v1 = b1[q];
                    t0a = ffma2(v0.x, df2[2*q],   t0a);
                    t0b = ffma2(v0.y, df2[2*q+1], t0b);
                    t1a = ffma2(v1.x, df2[2*q],   t1a);
                    t1b = ffma2(v1.y, df2[2*q+1], t1b);
                }
                float l0f, h0f, l1f, h1f;
                unpack2(add2(t0a, t0b), l0f, h0f);
                unpack2(add2(t1a, t1b), l1f, h1f);
                u64 tt2 = pack2(l0f + h0f, l1f + h1f);
                u64 al2 = *(const u64*)(arow + 2 * jp);        // LDS.64 broadcast
                u64 w2  = ffma2(TWO2, tt2, al2);               // alpha + 2*tt
                // K = exp(dj^2 - S) = ex2((dj^2 - S)*log2e), arg <= 0 always
                u64 d2   = df2[jp];
                u64 dl2  = mul2(d2, L2E2);
                u64 arg2 = ffma2(d2, dl2, nS2);
                float a0, a1;
                unpack2(arg2, a0, a1);
                u64 ej2 = pack2(ex2f(a0), ex2f(a1));
                acc2[jp] = ffma2(ej2, w2, acc2[jp]);
            }
        }
    }

    // write split-l partials (deterministic reduction in second kernel)
    if (i < NN) {
        float* dst = &g_partial[((size_t)blockIdx.y * NN + i) * DD];
        #pragma unroll
        for (int q = 0; q < 6; q++) {
            float x0, x1, x2, x3;
            unpack2(acc2[2*q],   x0, x1);
            unpack2(acc2[2*q+1], x2, x3);
            ((float4*)dst)[q] = make_float4(x0, x1, x2, x3);
        }
    }
}

__global__ void notears_reduce(float* __restrict__ out) {
    const int idx = blockIdx.x * blockDim.x + threadIdx.x;   // float4 granularity
    if (idx < NN * DD / 4) {
        const float4* p = (const float4*)g_partial;
        float4 s = make_float4(0.f, 0.f, 0.f, 0.f);
        #pragma unroll
        for (int q = 0; q < LSPLIT; q++) {
            float4 v = p[(size_t)q * (NN * DD / 4) + idx];
            s.x += v.x; s.y += v.y; s.z += v.z; s.w += v.w;
        }
        ((float4*)out)[idx] = s;
    }
}

extern "C" void kernel_launch(void* const* d_in, const int* in_sizes, int n_in,
                              void* d_out, int out_size) {
    const float* x     = (const float*)d_in[0];
    const float* alpha = (const float*)d_in[1];
    const float* beta  = (const float*)d_in[2];

    dim3 grid(NIB, LSPLIT);
    notears_main<<<grid, BLK>>>(x, alpha, beta);
    notears_reduce<<<(NN * DD / 4 + 255) / 256, 256>>>((float*)d_out);
}